// round 2
// baseline (speedup 1.0000x reference)
#include <cuda_runtime.h>
#include <cuda_bf16.h>
#include <math.h>

// Problem constants
#define S 2048
#define H 2048
#define NH 16
#define HD 128
#define QKV_N (3 * H)        // 6144
#define MIXED_W (3 * HD * NH) // 6144, row width of mixed buffer
#define HEAD_W (3 * HD)      // 384 per head in mixed row

// Scratch (allowed: __device__ globals, allocated at module load)
__device__ float g_mixed[(size_t)S * QKV_N];   // [s][nh][3*HD]
__device__ float g_ctx[(size_t)S * H];         // [s][nh*HD]

// ---------------------------------------------------------------------------
// Tiled NT SGEMM: C[M,N] = A[M,K] * B[N,K]^T + bias[n]
// BM=BN=128, BK=8, 256 threads, 8x8 per thread with interleaved mapping
// (row = ty + 16*i, col = tx + 16*j) -> conflict-free scalar LDS.
// ---------------------------------------------------------------------------
#define GBM 128
#define GBN 128
#define GBK 8

__global__ __launch_bounds__(256) void gemm_nt_kernel(
    const float* __restrict__ A, const float* __restrict__ B,
    const float* __restrict__ bias, float* __restrict__ C,
    int M, int N, int K)
{
    __shared__ float As[GBK][GBM];
    __shared__ float Bs[GBK][GBN];

    const int tid = threadIdx.x;
    const int tx = tid & 15;
    const int ty = tid >> 4;
    const int bm = blockIdx.y * GBM;
    const int bn = blockIdx.x * GBN;

    float acc[8][8];
#pragma unroll
    for (int i = 0; i < 8; i++)
#pragma unroll
        for (int j = 0; j < 8; j++) acc[i][j] = 0.f;

    const int lrow = tid >> 1;        // 0..127
    const int lk4  = (tid & 1) * 4;   // 0 or 4
    const float* Aptr = A + (size_t)(bm + lrow) * K + lk4;
    const float* Bptr = B + (size_t)(bn + lrow) * K + lk4;

    for (int k0 = 0; k0 < K; k0 += GBK) {
        float4 av = *(const float4*)(Aptr + k0);
        float4 bv = *(const float4*)(Bptr + k0);
        As[lk4 + 0][lrow] = av.x;
        As[lk4 + 1][lrow] = av.y;
        As[lk4 + 2][lrow] = av.z;
        As[lk4 + 3][lrow] = av.w;
        Bs[lk4 + 0][lrow] = bv.x;
        Bs[lk4 + 1][lrow] = bv.y;
        Bs[lk4 + 2][lrow] = bv.z;
        Bs[lk4 + 3][lrow] = bv.w;
        __syncthreads();

#pragma unroll
        for (int kk = 0; kk < GBK; kk++) {
            float a[8], b[8];
#pragma unroll
            for (int i = 0; i < 8; i++) a[i] = As[kk][ty + 16 * i];
#pragma unroll
            for (int j = 0; j < 8; j++) b[j] = Bs[kk][tx + 16 * j];
#pragma unroll
            for (int i = 0; i < 8; i++)
#pragma unroll
                for (int j = 0; j < 8; j++) acc[i][j] += a[i] * b[j];
        }
        __syncthreads();
    }

#pragma unroll
    for (int i = 0; i < 8; i++) {
        const int row = bm + ty + 16 * i;
#pragma unroll
        for (int j = 0; j < 8; j++) {
            const int col = bn + tx + 16 * j;
            float v = acc[i][j];
            if (bias) v += bias[col];
            C[(size_t)row * N + col] = v;
        }
    }
}

// ---------------------------------------------------------------------------
// Rotary embedding, in place on g_mixed. grid (S, NH), 64 threads.
// q at offset 0, k at offset 128 within each 384-wide head slot.
// out[d]    = x[d]*cos - x[d+64]*sin
// out[d+64] = x[d+64]*cos + x[d]*sin
// ---------------------------------------------------------------------------
__global__ void rotary_kernel(float* __restrict__ mixed)
{
    const int s = blockIdx.x;
    const int n = blockIdx.y;
    const int d = threadIdx.x;  // 0..63
    // inv_freq = 10000^(-d/64)
    const float inv_freq = expf(-(float)d * (9.210340371976184f / 64.0f));
    const float freq = (float)s * inv_freq;
    float si, c;
    sincosf(freq, &si, &c);

    float* base = mixed + (size_t)s * MIXED_W + n * HEAD_W;
#pragma unroll
    for (int which = 0; which < 2; which++) {
        float* p = base + which * HD;
        const float x1 = p[d];
        const float x2 = p[d + 64];
        p[d]      = x1 * c - x2 * si;
        p[d + 64] = x2 * c + x1 * si;
    }
}

// ---------------------------------------------------------------------------
// Flash attention (causal), fp32, per (q-tile of 64, head) block, 256 threads.
// Online softmax. Interleaved thread mapping -> conflict-free scalar LDS.
// ---------------------------------------------------------------------------
#define ATM 64
#define ATN 64
#define QSTR (HD + 1)   // 129
#define SSTR (ATN + 1)  // 65
// smem floats: 3*64*129 + 64*65 + 3*64 = 24768 + 4160 + 192 = 29120
#define ATTN_SMEM_BYTES (29120 * 4)

__global__ __launch_bounds__(256) void attn_kernel(
    const float* __restrict__ mixed, float* __restrict__ ctx)
{
    extern __shared__ float sm[];
    float* Qs   = sm;                     // 64 x 129
    float* Ks   = Qs + ATM * QSTR;        // 64 x 129
    float* Vs   = Ks + ATN * QSTR;        // 64 x 129
    float* Sb   = Vs + ATN * QSTR;        // 64 x 65
    float* rowm = Sb + ATM * SSTR;        // 64
    float* rowl = rowm + ATM;             // 64
    float* rsc  = rowl + ATM;             // 64

    const int qt = blockIdx.x;            // 0..31
    const int h  = blockIdx.y;            // 0..15
    const int tid = threadIdx.x;
    const int tx = tid & 15;
    const int ty = tid >> 4;
    const int r0 = qt * ATM;
    const float scale = 0.08838834764831845f;  // 1/sqrt(128)

    // Load Q (scaled)
    const float* qbase = mixed + (size_t)r0 * MIXED_W + h * HEAD_W;
    for (int idx = tid; idx < ATM * HD; idx += 256) {
        const int r = idx >> 7, d = idx & 127;
        Qs[r * QSTR + d] = qbase[(size_t)r * MIXED_W + d] * scale;
    }
    if (tid < ATM) { rowm[tid] = -1e30f; rowl[tid] = 0.f; }

    float acc[4][8];
#pragma unroll
    for (int i = 0; i < 4; i++)
#pragma unroll
        for (int j = 0; j < 8; j++) acc[i][j] = 0.f;

    for (int kt = 0; kt <= qt; kt++) {
        const int c0 = kt * ATN;
        __syncthreads();  // previous PV done (and Q load on first iter)

        const float* kbase = mixed + (size_t)c0 * MIXED_W + h * HEAD_W + HD;
        const float* vbase = kbase + HD;
        for (int idx = tid; idx < ATN * HD; idx += 256) {
            const int r = idx >> 7, d = idx & 127;
            Ks[r * QSTR + d] = kbase[(size_t)r * MIXED_W + d];
            Vs[r * QSTR + d] = vbase[(size_t)r * MIXED_W + d];
        }
        __syncthreads();

        // S = Q * K^T  (rows ty+16i, cols tx+16j)
        float sacc[4][4];
#pragma unroll
        for (int i = 0; i < 4; i++)
#pragma unroll
            for (int j = 0; j < 4; j++) sacc[i][j] = 0.f;

        for (int d = 0; d < HD; d++) {
            float a[4], b[4];
#pragma unroll
            for (int i = 0; i < 4; i++) a[i] = Qs[(ty + 16 * i) * QSTR + d];
#pragma unroll
            for (int j = 0; j < 4; j++) b[j] = Ks[(tx + 16 * j) * QSTR + d];
#pragma unroll
            for (int i = 0; i < 4; i++)
#pragma unroll
                for (int j = 0; j < 4; j++) sacc[i][j] += a[i] * b[j];
        }

        if (kt == qt) {
#pragma unroll
            for (int i = 0; i < 4; i++) {
                const int rg = r0 + ty + 16 * i;
#pragma unroll
                for (int j = 0; j < 4; j++) {
                    const int cg = c0 + tx + 16 * j;
                    Sb[(ty + 16 * i) * SSTR + tx + 16 * j] =
                        (cg > rg) ? -1e30f : sacc[i][j];
                }
            }
        } else {
#pragma unroll
            for (int i = 0; i < 4; i++)
#pragma unroll
                for (int j = 0; j < 4; j++)
                    Sb[(ty + 16 * i) * SSTR + tx + 16 * j] = sacc[i][j];
        }
        __syncthreads();

        // Online softmax: one thread per row
        if (tid < ATM) {
            float* srow = Sb + tid * SSTR;
            const float m_old = rowm[tid];
            float m_new = m_old;
#pragma unroll 8
            for (int c = 0; c < ATN; c++) m_new = fmaxf(m_new, srow[c]);
            const float sc = __expf(m_old - m_new);
            float l = rowl[tid] * sc;
#pragma unroll 8
            for (int c = 0; c < ATN; c++) {
                const float p = __expf(srow[c] - m_new);
                srow[c] = p;
                l += p;
            }
            rowm[tid] = m_new;
            rowl[tid] = l;
            rsc[tid]  = sc;
        }
        __syncthreads();

        // Rescale accumulators, then O += P * V (dims tx+16j)
#pragma unroll
        for (int i = 0; i < 4; i++) {
            const float scl = rsc[ty + 16 * i];
#pragma unroll
            for (int j = 0; j < 8; j++) acc[i][j] *= scl;
        }
        for (int c = 0; c < ATN; c++) {
            float p[4], v[8];
#pragma unroll
            for (int i = 0; i < 4; i++) p[i] = Sb[(ty + 16 * i) * SSTR + c];
#pragma unroll
            for (int j = 0; j < 8; j++) v[j] = Vs[c * QSTR + tx + 16 * j];
#pragma unroll
            for (int i = 0; i < 4; i++)
#pragma unroll
                for (int j = 0; j < 8; j++) acc[i][j] += p[i] * v[j];
        }
    }

    // Normalize and write ctx[s][h*128 + d]
#pragma unroll
    for (int i = 0; i < 4; i++) {
        const int r = ty + 16 * i;
        const float linv = 1.0f / rowl[r];
#pragma unroll
        for (int j = 0; j < 8; j++) {
            ctx[(size_t)(r0 + r) * H + h * HD + tx + 16 * j] = acc[i][j] * linv;
        }
    }
}

// ---------------------------------------------------------------------------
// Launch
// ---------------------------------------------------------------------------
extern "C" void kernel_launch(void* const* d_in, const int* in_sizes, int n_in,
                              void* d_out, int out_size)
{
    const float* hidden  = (const float*)d_in[0];
    // d_in[1] = attention_mask (deterministic causal triu) — not needed
    const float* w_qkv   = (const float*)d_in[2];
    const float* b_qkv   = (const float*)d_in[3];
    const float* w_dense = (const float*)d_in[4];
    float* out = (float*)d_out;

    float* mixed; float* ctx;
    cudaGetSymbolAddress((void**)&mixed, g_mixed);
    cudaGetSymbolAddress((void**)&ctx, g_ctx);

    cudaFuncSetAttribute(attn_kernel,
                         cudaFuncAttributeMaxDynamicSharedMemorySize,
                         ATTN_SMEM_BYTES);

    // 1) QKV projection: mixed[S, 6144] = hidden[S,2048] * w_qkv[6144,2048]^T + b
    {
        dim3 grid(QKV_N / GBN, S / GBM);
        gemm_nt_kernel<<<grid, 256>>>(hidden, w_qkv, b_qkv, mixed, S, QKV_N, H);
    }

    // 2) Rotary on q,k in place
    {
        dim3 grid(S, NH);
        rotary_kernel<<<grid, 64>>>(mixed);
    }

    // 3) Causal flash attention -> ctx[S, H]
    {
        dim3 grid(S / ATM, NH);
        attn_kernel<<<grid, 256, ATTN_SMEM_BYTES>>>(mixed, ctx);
    }

    // 4) Dense projection: out[S,2048] = ctx[S,2048] * w_dense[2048,2048]^T
    {
        dim3 grid(H / GBN, S / GBM);
        gemm_nt_kernel<<<grid, 256>>>(ctx, w_dense, nullptr, out, S, H, H);
    }
}

// round 5
// speedup vs baseline: 1.9732x; 1.9732x over previous
#include <cuda_runtime.h>
#include <cuda_bf16.h>
#include <math.h>
#include <stdint.h>

// Problem constants
#define S 2048
#define H 2048
#define NH 16
#define HD 128
#define QKV_N (3 * H)         // 6144
#define MIXED_W (3 * HD * NH) // 6144
#define HEAD_W (3 * HD)       // 384

// Scratch
__device__ float g_mixed[(size_t)S * QKV_N];
__device__ float g_ctx[(size_t)S * H];

// ---------------------------------------------------------------------------
// Helpers
// ---------------------------------------------------------------------------
__device__ __forceinline__ uint32_t smem_to_u32(const void* p) {
    uint32_t a;
    asm("{ .reg .u64 t; cvta.to.shared.u64 t, %1; cvt.u32.u64 %0, t; }" : "=r"(a) : "l"(p));
    return a;
}
__device__ __forceinline__ uint32_t f32_to_tf32(float f) {
    uint32_t r;
    asm("cvt.rna.tf32.f32 %0, %1;" : "=r"(r) : "f"(f));
    return r;
}
#define CP_ASYNC16(dst, src) \
    asm volatile("cp.async.cg.shared.global [%0], [%1], 16;" :: "r"(dst), "l"(src) : "memory")
#define CP_ASYNC_COMMIT() asm volatile("cp.async.commit_group;" ::: "memory")
#define CP_ASYNC_WAIT(n)  asm volatile("cp.async.wait_group %0;" :: "n"(n) : "memory")

__device__ __forceinline__ void mma_tf32(
    float c[4], const uint32_t a[4], const uint32_t b[2])
{
    asm volatile(
        "mma.sync.aligned.m16n8k8.row.col.f32.tf32.tf32.f32 "
        "{%0,%1,%2,%3}, {%4,%5,%6,%7}, {%8,%9}, {%0,%1,%2,%3};"
        : "+f"(c[0]), "+f"(c[1]), "+f"(c[2]), "+f"(c[3])
        : "r"(a[0]), "r"(a[1]), "r"(a[2]), "r"(a[3]), "r"(b[0]), "r"(b[1]));
}

// ---------------------------------------------------------------------------
// tf32 mma.sync GEMM: C[M,N] = A[M,K]*B[N,K]^T (+bias)
// BM=BN=128, BK=32, 128 threads (4 warps, 2x2 grid of 64x64 warp tiles).
// SMEM: [row][k] with row stride 36 floats -> conflict-free LDS fragments.
// cp.async double-buffered.
// ---------------------------------------------------------------------------
#define TSTR 36
#define TILE_WORDS (128 * TSTR)                 // 4608 floats per operand tile
#define GT_SMEM_BYTES (4 * TILE_WORDS * 4)      // A0,B0,A1,B1 = 73728 B

__global__ __launch_bounds__(128) void gemm_tc_kernel(
    const float* __restrict__ A, const float* __restrict__ B,
    const float* __restrict__ bias, float* __restrict__ C,
    int M, int N, int K)
{
    extern __shared__ float smf[];
    const uint32_t smem_base = smem_to_u32(smf);
    const int tid  = threadIdx.x;
    const int wid  = tid >> 5;
    const int lane = tid & 31;
    const int wm = wid & 1;          // warp M index (0..1)
    const int wn = wid >> 1;         // warp N index (0..1)
    const int bm = blockIdx.y * 128;
    const int bn = blockIdx.x * 128;

    const int lr = lane >> 2;        // 0..7
    const int lc = lane & 3;         // 0..3

    // cp.async staging: u = tid + 128*j ; m = u>>3 ; k4 = (u&7)*4
    const int ld_m  = tid >> 3;          // base row (advance by 16 per j)
    const int ld_k4 = (tid & 7) << 2;

    float c[4][8][4];
#pragma unroll
    for (int mt = 0; mt < 4; mt++)
#pragma unroll
        for (int nt = 0; nt < 8; nt++)
#pragma unroll
            for (int r = 0; r < 4; r++) c[mt][nt][r] = 0.f;

    const int NK = K >> 5;

    // issue loads for iteration i into buffer b
    auto load_tiles = [&](int i, int b) {
        const int k0 = i << 5;
        const uint32_t abase = smem_base + (uint32_t)(b * 2 * TILE_WORDS) * 4;
        const uint32_t bbase = abase + TILE_WORDS * 4;
#pragma unroll
        for (int j = 0; j < 8; j++) {
            const int m = ld_m + 16 * j;
            const uint32_t soff = (uint32_t)(m * TSTR + ld_k4) * 4;
            CP_ASYNC16(abase + soff, A + (size_t)(bm + m) * K + k0 + ld_k4);
            CP_ASYNC16(bbase + soff, B + (size_t)(bn + m) * K + k0 + ld_k4);
        }
        CP_ASYNC_COMMIT();
    };

    load_tiles(0, 0);

    for (int i = 0; i < NK; i++) {
        if (i + 1 < NK) {
            load_tiles(i + 1, (i + 1) & 1);
            CP_ASYNC_WAIT(1);
        } else {
            CP_ASYNC_WAIT(0);
        }
        __syncthreads();

        const float* As = smf + (size_t)(i & 1) * 2 * TILE_WORDS;
        const float* Bs = As + TILE_WORDS;

#pragma unroll
        for (int ks = 0; ks < 4; ks++) {
            const int kc = ks * 8 + lc;
            uint32_t af[4][4];
#pragma unroll
            for (int mt = 0; mt < 4; mt++) {
                const int row = wm * 64 + mt * 16 + lr;
                af[mt][0] = f32_to_tf32(As[row * TSTR + kc]);
                af[mt][1] = f32_to_tf32(As[(row + 8) * TSTR + kc]);
                af[mt][2] = f32_to_tf32(As[row * TSTR + kc + 4]);
                af[mt][3] = f32_to_tf32(As[(row + 8) * TSTR + kc + 4]);
            }
            uint32_t bf[8][2];
#pragma unroll
            for (int nt = 0; nt < 8; nt++) {
                const int ncol = wn * 64 + nt * 8 + lr;
                bf[nt][0] = f32_to_tf32(Bs[ncol * TSTR + kc]);
                bf[nt][1] = f32_to_tf32(Bs[ncol * TSTR + kc + 4]);
            }
#pragma unroll
            for (int mt = 0; mt < 4; mt++)
#pragma unroll
                for (int nt = 0; nt < 8; nt++)
                    mma_tf32(c[mt][nt], af[mt], bf[nt]);
        }
        __syncthreads();
    }

    // Epilogue: direct stores, float2 per (c0,c1)/(c2,c3)
#pragma unroll
    for (int nt = 0; nt < 8; nt++) {
        const int col = bn + wn * 64 + nt * 8 + lc * 2;
        float b0 = 0.f, b1 = 0.f;
        if (bias) { b0 = bias[col]; b1 = bias[col + 1]; }
#pragma unroll
        for (int mt = 0; mt < 4; mt++) {
            const int row = bm + wm * 64 + mt * 16 + lr;
            float2 v0 = make_float2(c[mt][nt][0] + b0, c[mt][nt][1] + b1);
            float2 v1 = make_float2(c[mt][nt][2] + b0, c[mt][nt][3] + b1);
            *(float2*)(C + (size_t)row * N + col) = v0;
            *(float2*)(C + (size_t)(row + 8) * N + col) = v1;
        }
    }
}

// ---------------------------------------------------------------------------
// Rotary embedding (unchanged, passing)
// ---------------------------------------------------------------------------
__global__ void rotary_kernel(float* __restrict__ mixed)
{
    const int s = blockIdx.x;
    const int n = blockIdx.y;
    const int d = threadIdx.x;  // 0..63
    const float inv_freq = expf(-(float)d * (9.210340371976184f / 64.0f));
    const float freq = (float)s * inv_freq;
    float si, c;
    sincosf(freq, &si, &c);

    float* base = mixed + (size_t)s * MIXED_W + n * HEAD_W;
#pragma unroll
    for (int which = 0; which < 2; which++) {
        float* p = base + which * HD;
        const float x1 = p[d];
        const float x2 = p[d + 64];
        p[d]      = x1 * c - x2 * si;
        p[d + 64] = x2 * c + x1 * si;
    }
}

// ---------------------------------------------------------------------------
// Flash attention (causal), fp32 (unchanged, passing)
// ---------------------------------------------------------------------------
#define ATM 64
#define ATN 64
#define QSTR (HD + 1)
#define SSTR (ATN + 1)
#define ATTN_SMEM_BYTES (29120 * 4)

__global__ __launch_bounds__(256) void attn_kernel(
    const float* __restrict__ mixed, float* __restrict__ ctx)
{
    extern __shared__ float sm[];
    float* Qs   = sm;
    float* Ks   = Qs + ATM * QSTR;
    float* Vs   = Ks + ATN * QSTR;
    float* Sb   = Vs + ATN * QSTR;
    float* rowm = Sb + ATM * SSTR;
    float* rowl = rowm + ATM;
    float* rsc  = rowl + ATM;

    const int qt = blockIdx.x;
    const int h  = blockIdx.y;
    const int tid = threadIdx.x;
    const int tx = tid & 15;
    const int ty = tid >> 4;
    const int r0 = qt * ATM;
    const float scale = 0.08838834764831845f;

    const float* qbase = mixed + (size_t)r0 * MIXED_W + h * HEAD_W;
    for (int idx = tid; idx < ATM * HD; idx += 256) {
        const int r = idx >> 7, d = idx & 127;
        Qs[r * QSTR + d] = qbase[(size_t)r * MIXED_W + d] * scale;
    }
    if (tid < ATM) { rowm[tid] = -1e30f; rowl[tid] = 0.f; }

    float acc[4][8];
#pragma unroll
    for (int i = 0; i < 4; i++)
#pragma unroll
        for (int j = 0; j < 8; j++) acc[i][j] = 0.f;

    for (int kt = 0; kt <= qt; kt++) {
        const int c0 = kt * ATN;
        __syncthreads();

        const float* kbase = mixed + (size_t)c0 * MIXED_W + h * HEAD_W + HD;
        const float* vbase = kbase + HD;
        for (int idx = tid; idx < ATN * HD; idx += 256) {
            const int r = idx >> 7, d = idx & 127;
            Ks[r * QSTR + d] = kbase[(size_t)r * MIXED_W + d];
            Vs[r * QSTR + d] = vbase[(size_t)r * MIXED_W + d];
        }
        __syncthreads();

        float sacc[4][4];
#pragma unroll
        for (int i = 0; i < 4; i++)
#pragma unroll
            for (int j = 0; j < 4; j++) sacc[i][j] = 0.f;

        for (int d = 0; d < HD; d++) {
            float a[4], b[4];
#pragma unroll
            for (int i = 0; i < 4; i++) a[i] = Qs[(ty + 16 * i) * QSTR + d];
#pragma unroll
            for (int j = 0; j < 4; j++) b[j] = Ks[(tx + 16 * j) * QSTR + d];
#pragma unroll
            for (int i = 0; i < 4; i++)
#pragma unroll
                for (int j = 0; j < 4; j++) sacc[i][j] += a[i] * b[j];
        }

        if (kt == qt) {
#pragma unroll
            for (int i = 0; i < 4; i++) {
                const int rg = r0 + ty + 16 * i;
#pragma unroll
                for (int j = 0; j < 4; j++) {
                    const int cg = c0 + tx + 16 * j;
                    Sb[(ty + 16 * i) * SSTR + tx + 16 * j] =
                        (cg > rg) ? -1e30f : sacc[i][j];
                }
            }
        } else {
#pragma unroll
            for (int i = 0; i < 4; i++)
#pragma unroll
                for (int j = 0; j < 4; j++)
                    Sb[(ty + 16 * i) * SSTR + tx + 16 * j] = sacc[i][j];
        }
        __syncthreads();

        if (tid < ATM) {
            float* srow = Sb + tid * SSTR;
            const float m_old = rowm[tid];
            float m_new = m_old;
#pragma unroll 8
            for (int c = 0; c < ATN; c++) m_new = fmaxf(m_new, srow[c]);
            const float sc = __expf(m_old - m_new);
            float l = rowl[tid] * sc;
#pragma unroll 8
            for (int c = 0; c < ATN; c++) {
                const float p = __expf(srow[c] - m_new);
                srow[c] = p;
                l += p;
            }
            rowm[tid] = m_new;
            rowl[tid] = l;
            rsc[tid]  = sc;
        }
        __syncthreads();

#pragma unroll
        for (int i = 0; i < 4; i++) {
            const float scl = rsc[ty + 16 * i];
#pragma unroll
            for (int j = 0; j < 8; j++) acc[i][j] *= scl;
        }
        for (int c = 0; c < ATN; c++) {
            float p[4], v[8];
#pragma unroll
            for (int i = 0; i < 4; i++) p[i] = Sb[(ty + 16 * i) * SSTR + c];
#pragma unroll
            for (int j = 0; j < 8; j++) v[j] = Vs[c * QSTR + tx + 16 * j];
#pragma unroll
            for (int i = 0; i < 4; i++)
#pragma unroll
                for (int j = 0; j < 8; j++) acc[i][j] += p[i] * v[j];
        }
    }

#pragma unroll
    for (int i = 0; i < 4; i++) {
        const int r = ty + 16 * i;
        const float linv = 1.0f / rowl[r];
#pragma unroll
        for (int j = 0; j < 8; j++) {
            ctx[(size_t)(r0 + r) * H + h * HD + tx + 16 * j] = acc[i][j] * linv;
        }
    }
}

// ---------------------------------------------------------------------------
// Launch
// ---------------------------------------------------------------------------
extern "C" void kernel_launch(void* const* d_in, const int* in_sizes, int n_in,
                              void* d_out, int out_size)
{
    const float* hidden  = (const float*)d_in[0];
    const float* w_qkv   = (const float*)d_in[2];
    const float* b_qkv   = (const float*)d_in[3];
    const float* w_dense = (const float*)d_in[4];
    float* out = (float*)d_out;

    float* mixed; float* ctx;
    cudaGetSymbolAddress((void**)&mixed, g_mixed);
    cudaGetSymbolAddress((void**)&ctx, g_ctx);

    cudaFuncSetAttribute(gemm_tc_kernel,
                         cudaFuncAttributeMaxDynamicSharedMemorySize, GT_SMEM_BYTES);
    cudaFuncSetAttribute(attn_kernel,
                         cudaFuncAttributeMaxDynamicSharedMemorySize, ATTN_SMEM_BYTES);

    // 1) QKV projection (tf32 mma.sync)
    {
        dim3 grid(QKV_N / 128, S / 128);
        gemm_tc_kernel<<<grid, 128, GT_SMEM_BYTES>>>(hidden, w_qkv, b_qkv, mixed, S, QKV_N, H);
    }

    // 2) Rotary
    {
        dim3 grid(S, NH);
        rotary_kernel<<<grid, 64>>>(mixed);
    }

    // 3) Causal flash attention
    {
        dim3 grid(S / ATM, NH);
        attn_kernel<<<grid, 256, ATTN_SMEM_BYTES>>>(mixed, ctx);
    }

    // 4) Dense projection (tf32 mma.sync)
    {
        dim3 grid(H / 128, S / 128);
        gemm_tc_kernel<<<grid, 128, GT_SMEM_BYTES>>>(ctx, w_dense, nullptr, out, S, H, H);
    }
}

// round 6
// speedup vs baseline: 4.0934x; 2.0745x over previous
#include <cuda_runtime.h>
#include <cuda_bf16.h>
#include <math.h>
#include <stdint.h>

// Problem constants
#define S 2048
#define H 2048
#define NH 16
#define HD 128
#define QKV_N (3 * H)         // 6144
#define MIXED_W (3 * HD * NH) // 6144
#define HEAD_W (3 * HD)       // 384

// Scratch
__device__ float g_mixed[(size_t)S * QKV_N];
__device__ float g_ctx[(size_t)S * H];

// ---------------------------------------------------------------------------
// Helpers
// ---------------------------------------------------------------------------
__device__ __forceinline__ uint32_t smem_to_u32(const void* p) {
    uint32_t a;
    asm("{ .reg .u64 t; cvta.to.shared.u64 t, %1; cvt.u32.u64 %0, t; }" : "=r"(a) : "l"(p));
    return a;
}
__device__ __forceinline__ uint32_t f32_to_tf32(float f) {
    uint32_t r;
    asm("cvt.rna.tf32.f32 %0, %1;" : "=r"(r) : "f"(f));
    return r;
}
#define CP_ASYNC16(dst, src) \
    asm volatile("cp.async.cg.shared.global [%0], [%1], 16;" :: "r"(dst), "l"(src) : "memory")
#define CP_ASYNC_COMMIT() asm volatile("cp.async.commit_group;" ::: "memory")
#define CP_ASYNC_WAIT(n)  asm volatile("cp.async.wait_group %0;" :: "n"(n) : "memory")

__device__ __forceinline__ void mma_tf32(
    float c[4], const uint32_t a[4], const uint32_t b[2])
{
    asm volatile(
        "mma.sync.aligned.m16n8k8.row.col.f32.tf32.tf32.f32 "
        "{%0,%1,%2,%3}, {%4,%5,%6,%7}, {%8,%9}, {%0,%1,%2,%3};"
        : "+f"(c[0]), "+f"(c[1]), "+f"(c[2]), "+f"(c[3])
        : "r"(a[0]), "r"(a[1]), "r"(a[2]), "r"(a[3]), "r"(b[0]), "r"(b[1]));
}

// ---------------------------------------------------------------------------
// tf32 mma.sync GEMM: C[M,N] = A[M,K]*B[N,K]^T (+bias)   (unchanged, passing)
// ---------------------------------------------------------------------------
#define TSTR 36
#define TILE_WORDS (128 * TSTR)
#define GT_SMEM_BYTES (4 * TILE_WORDS * 4)

__global__ __launch_bounds__(128) void gemm_tc_kernel(
    const float* __restrict__ A, const float* __restrict__ B,
    const float* __restrict__ bias, float* __restrict__ C,
    int M, int N, int K)
{
    extern __shared__ float smf[];
    const uint32_t smem_base = smem_to_u32(smf);
    const int tid  = threadIdx.x;
    const int wid  = tid >> 5;
    const int lane = tid & 31;
    const int wm = wid & 1;
    const int wn = wid >> 1;
    const int bm = blockIdx.y * 128;
    const int bn = blockIdx.x * 128;

    const int lr = lane >> 2;
    const int lc = lane & 3;

    const int ld_m  = tid >> 3;
    const int ld_k4 = (tid & 7) << 2;

    float c[4][8][4];
#pragma unroll
    for (int mt = 0; mt < 4; mt++)
#pragma unroll
        for (int nt = 0; nt < 8; nt++)
#pragma unroll
            for (int r = 0; r < 4; r++) c[mt][nt][r] = 0.f;

    const int NK = K >> 5;

    auto load_tiles = [&](int i, int b) {
        const int k0 = i << 5;
        const uint32_t abase = smem_base + (uint32_t)(b * 2 * TILE_WORDS) * 4;
        const uint32_t bbase = abase + TILE_WORDS * 4;
#pragma unroll
        for (int j = 0; j < 8; j++) {
            const int m = ld_m + 16 * j;
            const uint32_t soff = (uint32_t)(m * TSTR + ld_k4) * 4;
            CP_ASYNC16(abase + soff, A + (size_t)(bm + m) * K + k0 + ld_k4);
            CP_ASYNC16(bbase + soff, B + (size_t)(bn + m) * K + k0 + ld_k4);
        }
        CP_ASYNC_COMMIT();
    };

    load_tiles(0, 0);

    for (int i = 0; i < NK; i++) {
        if (i + 1 < NK) {
            load_tiles(i + 1, (i + 1) & 1);
            CP_ASYNC_WAIT(1);
        } else {
            CP_ASYNC_WAIT(0);
        }
        __syncthreads();

        const float* As = smf + (size_t)(i & 1) * 2 * TILE_WORDS;
        const float* Bs = As + TILE_WORDS;

#pragma unroll
        for (int ks = 0; ks < 4; ks++) {
            const int kc = ks * 8 + lc;
            uint32_t af[4][4];
#pragma unroll
            for (int mt = 0; mt < 4; mt++) {
                const int row = wm * 64 + mt * 16 + lr;
                af[mt][0] = f32_to_tf32(As[row * TSTR + kc]);
                af[mt][1] = f32_to_tf32(As[(row + 8) * TSTR + kc]);
                af[mt][2] = f32_to_tf32(As[row * TSTR + kc + 4]);
                af[mt][3] = f32_to_tf32(As[(row + 8) * TSTR + kc + 4]);
            }
            uint32_t bf[8][2];
#pragma unroll
            for (int nt = 0; nt < 8; nt++) {
                const int ncol = wn * 64 + nt * 8 + lr;
                bf[nt][0] = f32_to_tf32(Bs[ncol * TSTR + kc]);
                bf[nt][1] = f32_to_tf32(Bs[ncol * TSTR + kc + 4]);
            }
#pragma unroll
            for (int mt = 0; mt < 4; mt++)
#pragma unroll
                for (int nt = 0; nt < 8; nt++)
                    mma_tf32(c[mt][nt], af[mt], bf[nt]);
        }
        __syncthreads();
    }

#pragma unroll
    for (int nt = 0; nt < 8; nt++) {
        const int col = bn + wn * 64 + nt * 8 + lc * 2;
        float b0 = 0.f, b1 = 0.f;
        if (bias) { b0 = bias[col]; b1 = bias[col + 1]; }
#pragma unroll
        for (int mt = 0; mt < 4; mt++) {
            const int row = bm + wm * 64 + mt * 16 + lr;
            float2 v0 = make_float2(c[mt][nt][0] + b0, c[mt][nt][1] + b1);
            float2 v1 = make_float2(c[mt][nt][2] + b0, c[mt][nt][3] + b1);
            *(float2*)(C + (size_t)row * N + col) = v0;
            *(float2*)(C + (size_t)(row + 8) * N + col) = v1;
        }
    }
}

// ---------------------------------------------------------------------------
// Rotary embedding (unchanged, passing)
// ---------------------------------------------------------------------------
__global__ void rotary_kernel(float* __restrict__ mixed)
{
    const int s = blockIdx.x;
    const int n = blockIdx.y;
    const int d = threadIdx.x;  // 0..63
    const float inv_freq = expf(-(float)d * (9.210340371976184f / 64.0f));
    const float freq = (float)s * inv_freq;
    float si, c;
    sincosf(freq, &si, &c);

    float* base = mixed + (size_t)s * MIXED_W + n * HEAD_W;
#pragma unroll
    for (int which = 0; which < 2; which++) {
        float* p = base + which * HD;
        const float x1 = p[d];
        const float x2 = p[d + 64];
        p[d]      = x1 * c - x2 * si;
        p[d + 64] = x2 * c + x1 * si;
    }
}

// ---------------------------------------------------------------------------
// tf32 mma.sync flash attention (causal)
// CTA: 128 q-rows x 1 head, 4 warps (32 rows each). K-tiles of 64, cp.async
// double-buffered. P kept in registers via quad shuffles. Softmax in regs.
// Q/K stride 132 (==4 mod 32), V stride 136 (==8 mod 32): conflict-free LDS.
// ---------------------------------------------------------------------------
#define AQ 128
#define AK 64
#define QST 132
#define VST 136
#define QWRD (128 * QST)            // 16896 words
#define KWRD (64 * QST)             // 8448 words
#define VWRD (64 * VST)             // 8704 words
#define ATTN_SMEM_BYTES ((QWRD + 2 * (KWRD + VWRD)) * 4)  // 204800 B

__global__ __launch_bounds__(128, 1) void attn_tc_kernel(
    const float* __restrict__ mixed, float* __restrict__ ctx)
{
    extern __shared__ float sf[];
    float* Qs = sf;
    const uint32_t smem_base = smem_to_u32(sf);

    const int tid  = threadIdx.x;
    const int wid  = tid >> 5;
    const int lane = tid & 31;
    const int lr = lane >> 2;
    const int lc = lane & 3;
    const int qt = gridDim.x - 1 - blockIdx.x;   // biggest tiles first
    const int h  = blockIdx.y;
    const int r0 = qt * AQ;
    const int m0 = wid * 32;
    const float scale = 0.08838834764831845f;    // 1/sqrt(128)
    const size_t hoff = (size_t)h * HEAD_W;

    auto load_kv = [&](int kt) {
        const int b = kt & 1;
        const uint32_t kb = smem_base + (uint32_t)(QWRD + b * (KWRD + VWRD)) * 4;
        const uint32_t vb = kb + KWRD * 4;
        const float* kg = mixed + (size_t)(kt * AK) * MIXED_W + hoff + HD;
        const float* vg = kg + HD;
#pragma unroll
        for (int it = 0; it < 16; it++) {
            const int u = tid + (it << 7);
            const int row = u >> 5, c4 = (u & 31) << 2;
            CP_ASYNC16(kb + (uint32_t)(row * QST + c4) * 4, kg + (size_t)row * MIXED_W + c4);
            CP_ASYNC16(vb + (uint32_t)(row * VST + c4) * 4, vg + (size_t)row * MIXED_W + c4);
        }
        CP_ASYNC_COMMIT();
    };

    load_kv(0);

    // stage Q (scaled)
    {
        const float* qg = mixed + (size_t)r0 * MIXED_W + hoff;
#pragma unroll
        for (int it = 0; it < 32; it++) {
            const int u = tid + (it << 7);
            const int row = u >> 5, c4 = (u & 31) << 2;
            float4 v = *(const float4*)(qg + (size_t)row * MIXED_W + c4);
            float* d = Qs + row * QST + c4;
            d[0] = v.x * scale; d[1] = v.y * scale;
            d[2] = v.z * scale; d[3] = v.w * scale;
        }
    }

    const int nkt = (r0 >> 6) + 2;

    float co[2][16][4];
#pragma unroll
    for (int mt = 0; mt < 2; mt++)
#pragma unroll
        for (int nt = 0; nt < 16; nt++)
#pragma unroll
            for (int r = 0; r < 4; r++) co[mt][nt][r] = 0.f;
    float mrow[2][2] = {{-1e30f, -1e30f}, {-1e30f, -1e30f}};
    float lrow[2][2] = {{0.f, 0.f}, {0.f, 0.f}};

    const int src1 = (lane & ~3) | (lc >> 1);
    const int src2 = src1 + 2;
    const bool podd = (lc & 1);

    for (int kt = 0; kt < nkt; kt++) {
        if (kt + 1 < nkt) { load_kv(kt + 1); CP_ASYNC_WAIT(1); }
        else              { CP_ASYNC_WAIT(0); }
        __syncthreads();

        const float* Ks = sf + QWRD + (size_t)(kt & 1) * (KWRD + VWRD);
        const float* Vs = Ks + KWRD;
        const int c0 = kt * AK;

        // ---- S = Q K^T ----
        float s[2][8][4];
#pragma unroll
        for (int mt = 0; mt < 2; mt++)
#pragma unroll
            for (int nt = 0; nt < 8; nt++)
#pragma unroll
                for (int r = 0; r < 4; r++) s[mt][nt][r] = 0.f;

#pragma unroll
        for (int ks = 0; ks < 16; ks++) {
            const int kc = ks * 8 + lc;
            uint32_t af[2][4];
#pragma unroll
            for (int mt = 0; mt < 2; mt++) {
                const int row = m0 + mt * 16 + lr;
                af[mt][0] = f32_to_tf32(Qs[row * QST + kc]);
                af[mt][1] = f32_to_tf32(Qs[(row + 8) * QST + kc]);
                af[mt][2] = f32_to_tf32(Qs[row * QST + kc + 4]);
                af[mt][3] = f32_to_tf32(Qs[(row + 8) * QST + kc + 4]);
            }
#pragma unroll
            for (int nt = 0; nt < 8; nt++) {
                const int ncol = nt * 8 + lr;
                uint32_t bf[2];
                bf[0] = f32_to_tf32(Ks[ncol * QST + kc]);
                bf[1] = f32_to_tf32(Ks[ncol * QST + kc + 4]);
                mma_tf32(s[0][nt], af[0], bf);
                mma_tf32(s[1][nt], af[1], bf);
            }
        }

        // ---- causal mask (only tiles touching the diagonal) ----
        if (c0 + AK - 1 > r0 + m0) {
#pragma unroll
            for (int mt = 0; mt < 2; mt++) {
                const int rga = r0 + m0 + mt * 16 + lr;
                const int rgb = rga + 8;
#pragma unroll
                for (int nt = 0; nt < 8; nt++) {
                    const int cg0 = c0 + nt * 8 + lc * 2;
                    const int cg1 = cg0 + 1;
                    if (cg0 > rga) s[mt][nt][0] = -1e30f;
                    if (cg1 > rga) s[mt][nt][1] = -1e30f;
                    if (cg0 > rgb) s[mt][nt][2] = -1e30f;
                    if (cg1 > rgb) s[mt][nt][3] = -1e30f;
                }
            }
        }

        // ---- online softmax (registers + quad shuffles) ----
#pragma unroll
        for (int mt = 0; mt < 2; mt++) {
#pragma unroll
            for (int hh = 0; hh < 2; hh++) {
                float mx = -1e30f;
#pragma unroll
                for (int nt = 0; nt < 8; nt++)
                    mx = fmaxf(mx, fmaxf(s[mt][nt][2 * hh], s[mt][nt][2 * hh + 1]));
                mx = fmaxf(mx, __shfl_xor_sync(0xffffffffu, mx, 1));
                mx = fmaxf(mx, __shfl_xor_sync(0xffffffffu, mx, 2));
                const float m_new = fmaxf(mrow[mt][hh], mx);
                const float sc = __expf(mrow[mt][hh] - m_new);
                float rs = 0.f;
#pragma unroll
                for (int nt = 0; nt < 8; nt++) {
                    const float p0 = __expf(s[mt][nt][2 * hh] - m_new);
                    const float p1 = __expf(s[mt][nt][2 * hh + 1] - m_new);
                    s[mt][nt][2 * hh] = p0;
                    s[mt][nt][2 * hh + 1] = p1;
                    rs += p0 + p1;
                }
                rs += __shfl_xor_sync(0xffffffffu, rs, 1);
                rs += __shfl_xor_sync(0xffffffffu, rs, 2);
                lrow[mt][hh] = lrow[mt][hh] * sc + rs;
                mrow[mt][hh] = m_new;
#pragma unroll
                for (int nt = 0; nt < 16; nt++) {
                    co[mt][nt][2 * hh]     *= sc;
                    co[mt][nt][2 * hh + 1] *= sc;
                }
            }
        }

        // ---- O += P V ----
#pragma unroll
        for (int kg = 0; kg < 8; kg++) {
            uint32_t pa[2][4];
#pragma unroll
            for (int mt = 0; mt < 2; mt++) {
                const float x0 = __shfl_sync(0xffffffffu, s[mt][kg][0], src1);
                const float x1 = __shfl_sync(0xffffffffu, s[mt][kg][1], src1);
                pa[mt][0] = f32_to_tf32(podd ? x1 : x0);
                const float x2 = __shfl_sync(0xffffffffu, s[mt][kg][2], src1);
                const float x3 = __shfl_sync(0xffffffffu, s[mt][kg][3], src1);
                pa[mt][1] = f32_to_tf32(podd ? x3 : x2);
                const float y0 = __shfl_sync(0xffffffffu, s[mt][kg][0], src2);
                const float y1 = __shfl_sync(0xffffffffu, s[mt][kg][1], src2);
                pa[mt][2] = f32_to_tf32(podd ? y1 : y0);
                const float y2 = __shfl_sync(0xffffffffu, s[mt][kg][2], src2);
                const float y3 = __shfl_sync(0xffffffffu, s[mt][kg][3], src2);
                pa[mt][3] = f32_to_tf32(podd ? y3 : y2);
            }
#pragma unroll
            for (int nt = 0; nt < 16; nt++) {
                uint32_t vb[2];
                vb[0] = f32_to_tf32(Vs[(kg * 8 + lc) * VST + nt * 8 + lr]);
                vb[1] = f32_to_tf32(Vs[(kg * 8 + lc + 4) * VST + nt * 8 + lr]);
                mma_tf32(co[0][nt], pa[0], vb);
                mma_tf32(co[1][nt], pa[1], vb);
            }
        }
        __syncthreads();
    }

    // ---- normalize + store ----
#pragma unroll
    for (int mt = 0; mt < 2; mt++) {
        const float li0 = 1.f / lrow[mt][0];
        const float li1 = 1.f / lrow[mt][1];
        const int row = r0 + m0 + mt * 16 + lr;
#pragma unroll
        for (int nt = 0; nt < 16; nt++) {
            const int col = h * HD + nt * 8 + lc * 2;
            *(float2*)(ctx + (size_t)row * H + col) =
                make_float2(co[mt][nt][0] * li0, co[mt][nt][1] * li0);
            *(float2*)(ctx + (size_t)(row + 8) * H + col) =
                make_float2(co[mt][nt][2] * li1, co[mt][nt][3] * li1);
        }
    }
}

// ---------------------------------------------------------------------------
// Launch
// ---------------------------------------------------------------------------
extern "C" void kernel_launch(void* const* d_in, const int* in_sizes, int n_in,
                              void* d_out, int out_size)
{
    const float* hidden  = (const float*)d_in[0];
    const float* w_qkv   = (const float*)d_in[2];
    const float* b_qkv   = (const float*)d_in[3];
    const float* w_dense = (const float*)d_in[4];
    float* out = (float*)d_out;

    float* mixed; float* ctx;
    cudaGetSymbolAddress((void**)&mixed, g_mixed);
    cudaGetSymbolAddress((void**)&ctx, g_ctx);

    cudaFuncSetAttribute(gemm_tc_kernel,
                         cudaFuncAttributeMaxDynamicSharedMemorySize, GT_SMEM_BYTES);
    cudaFuncSetAttribute(attn_tc_kernel,
                         cudaFuncAttributeMaxDynamicSharedMemorySize, ATTN_SMEM_BYTES);

    // 1) QKV projection (tf32 mma.sync)
    {
        dim3 grid(QKV_N / 128, S / 128);
        gemm_tc_kernel<<<grid, 128, GT_SMEM_BYTES>>>(hidden, w_qkv, b_qkv, mixed, S, QKV_N, H);
    }

    // 2) Rotary
    {
        dim3 grid(S, NH);
        rotary_kernel<<<grid, 64>>>(mixed);
    }

    // 3) Causal flash attention (tf32 mma.sync)
    {
        dim3 grid(S / AQ, NH);
        attn_tc_kernel<<<grid, 128, ATTN_SMEM_BYTES>>>(mixed, ctx);
    }

    // 4) Dense projection (tf32 mma.sync)
    {
        dim3 grid(H / 128, S / 128);
        gemm_tc_kernel<<<grid, 128, GT_SMEM_BYTES>>>(ctx, w_dense, nullptr, out, S, H, H);
    }
}

// round 7
// speedup vs baseline: 4.5265x; 1.1058x over previous
#include <cuda_runtime.h>
#include <cuda_bf16.h>
#include <math.h>
#include <stdint.h>

// Problem constants
#define S 2048
#define H 2048
#define NH 16
#define HD 128
#define QKV_N (3 * H)         // 6144
#define MIXED_W (3 * HD * NH) // 6144
#define HEAD_W (3 * HD)       // 384

// Scratch
__device__ float g_mixed[(size_t)S * QKV_N];
__device__ float g_ctx[(size_t)S * H];

// ---------------------------------------------------------------------------
// Helpers
// ---------------------------------------------------------------------------
__device__ __forceinline__ uint32_t smem_to_u32(const void* p) {
    uint32_t a;
    asm("{ .reg .u64 t; cvta.to.shared.u64 t, %1; cvt.u32.u64 %0, t; }" : "=r"(a) : "l"(p));
    return a;
}
__device__ __forceinline__ uint32_t f32_to_tf32(float f) {
    uint32_t r;
    asm("cvt.rna.tf32.f32 %0, %1;" : "=r"(r) : "f"(f));
    return r;
}
__device__ __forceinline__ float tf32_round(float f) {
    return __uint_as_float(f32_to_tf32(f));
}
#define CP_ASYNC16(dst, src) \
    asm volatile("cp.async.cg.shared.global [%0], [%1], 16;" :: "r"(dst), "l"(src) : "memory")
#define CP_ASYNC_COMMIT() asm volatile("cp.async.commit_group;" ::: "memory")
#define CP_ASYNC_WAIT(n)  asm volatile("cp.async.wait_group %0;" :: "n"(n) : "memory")

__device__ __forceinline__ void mma_tf32(
    float c[4], const uint32_t a[4], const uint32_t b[2])
{
    asm volatile(
        "mma.sync.aligned.m16n8k8.row.col.f32.tf32.tf32.f32 "
        "{%0,%1,%2,%3}, {%4,%5,%6,%7}, {%8,%9}, {%0,%1,%2,%3};"
        : "+f"(c[0]), "+f"(c[1]), "+f"(c[2]), "+f"(c[3])
        : "r"(a[0]), "r"(a[1]), "r"(a[2]), "r"(a[3]), "r"(b[0]), "r"(b[1]));
}

// ---------------------------------------------------------------------------
// tf32 mma.sync GEMM: C[M,N] = A[M,K]*B[N,K]^T (+bias)
// BM=BN=128, BK=32, 256 threads (8 warps, 2x4 grid of 64x32 warp tiles).
// ---------------------------------------------------------------------------
#define TSTR 36
#define TILE_WORDS (128 * TSTR)
#define GT_SMEM_BYTES (4 * TILE_WORDS * 4)

__global__ __launch_bounds__(256) void gemm_tc_kernel(
    const float* __restrict__ A, const float* __restrict__ B,
    const float* __restrict__ bias, float* __restrict__ C,
    int M, int N, int K)
{
    extern __shared__ float smf[];
    const uint32_t smem_base = smem_to_u32(smf);
    const int tid  = threadIdx.x;
    const int wid  = tid >> 5;
    const int lane = tid & 31;
    const int wm = wid >> 2;         // 0..1
    const int wn = wid & 3;          // 0..3
    const int bm = blockIdx.y * 128;
    const int bn = blockIdx.x * 128;

    const int lr = lane >> 2;
    const int lc = lane & 3;

    const int ld_m  = tid >> 3;          // 0..31
    const int ld_k4 = (tid & 7) << 2;

    float c[4][4][4];
#pragma unroll
    for (int mt = 0; mt < 4; mt++)
#pragma unroll
        for (int nt = 0; nt < 4; nt++)
#pragma unroll
            for (int r = 0; r < 4; r++) c[mt][nt][r] = 0.f;

    const int NK = K >> 5;

    auto load_tiles = [&](int i, int b) {
        const int k0 = i << 5;
        const uint32_t abase = smem_base + (uint32_t)(b * 2 * TILE_WORDS) * 4;
        const uint32_t bbase = abase + TILE_WORDS * 4;
#pragma unroll
        for (int j = 0; j < 4; j++) {
            const int m = ld_m + 32 * j;
            const uint32_t soff = (uint32_t)(m * TSTR + ld_k4) * 4;
            CP_ASYNC16(abase + soff, A + (size_t)(bm + m) * K + k0 + ld_k4);
            CP_ASYNC16(bbase + soff, B + (size_t)(bn + m) * K + k0 + ld_k4);
        }
        CP_ASYNC_COMMIT();
    };

    load_tiles(0, 0);

    for (int i = 0; i < NK; i++) {
        if (i + 1 < NK) {
            load_tiles(i + 1, (i + 1) & 1);
            CP_ASYNC_WAIT(1);
        } else {
            CP_ASYNC_WAIT(0);
        }
        __syncthreads();

        const float* As = smf + (size_t)(i & 1) * 2 * TILE_WORDS;
        const float* Bs = As + TILE_WORDS;

#pragma unroll
        for (int ks = 0; ks < 4; ks++) {
            const int kc = ks * 8 + lc;
            uint32_t af[4][4];
#pragma unroll
            for (int mt = 0; mt < 4; mt++) {
                const int row = wm * 64 + mt * 16 + lr;
                af[mt][0] = f32_to_tf32(As[row * TSTR + kc]);
                af[mt][1] = f32_to_tf32(As[(row + 8) * TSTR + kc]);
                af[mt][2] = f32_to_tf32(As[row * TSTR + kc + 4]);
                af[mt][3] = f32_to_tf32(As[(row + 8) * TSTR + kc + 4]);
            }
            uint32_t bf[4][2];
#pragma unroll
            for (int nt = 0; nt < 4; nt++) {
                const int ncol = wn * 32 + nt * 8 + lr;
                bf[nt][0] = f32_to_tf32(Bs[ncol * TSTR + kc]);
                bf[nt][1] = f32_to_tf32(Bs[ncol * TSTR + kc + 4]);
            }
#pragma unroll
            for (int mt = 0; mt < 4; mt++)
#pragma unroll
                for (int nt = 0; nt < 4; nt++)
                    mma_tf32(c[mt][nt], af[mt], bf[nt]);
        }
        __syncthreads();
    }

#pragma unroll
    for (int nt = 0; nt < 4; nt++) {
        const int col = bn + wn * 32 + nt * 8 + lc * 2;
        float b0 = 0.f, b1 = 0.f;
        if (bias) { b0 = bias[col]; b1 = bias[col + 1]; }
#pragma unroll
        for (int mt = 0; mt < 4; mt++) {
            const int row = bm + wm * 64 + mt * 16 + lr;
            float2 v0 = make_float2(c[mt][nt][0] + b0, c[mt][nt][1] + b1);
            float2 v1 = make_float2(c[mt][nt][2] + b0, c[mt][nt][3] + b1);
            *(float2*)(C + (size_t)row * N + col) = v0;
            *(float2*)(C + (size_t)(row + 8) * N + col) = v1;
        }
    }
}

// ---------------------------------------------------------------------------
// Rotary embedding + tf32 pre-round + q pre-scale (q,k rotated; v rounded)
// ---------------------------------------------------------------------------
__global__ void rotary_kernel(float* __restrict__ mixed)
{
    const int s = blockIdx.x;
    const int n = blockIdx.y;
    const int d = threadIdx.x;  // 0..63
    const float inv_freq = expf(-(float)d * (9.210340371976184f / 64.0f));
    const float freq = (float)s * inv_freq;
    float si, c;
    sincosf(freq, &si, &c);
    const float scale = 0.08838834764831845f;  // 1/sqrt(128)

    float* base = mixed + (size_t)s * MIXED_W + n * HEAD_W;
    // q (scaled)
    {
        float* p = base;
        const float x1 = p[d];
        const float x2 = p[d + 64];
        p[d]      = tf32_round(scale * (x1 * c - x2 * si));
        p[d + 64] = tf32_round(scale * (x2 * c + x1 * si));
    }
    // k
    {
        float* p = base + HD;
        const float x1 = p[d];
        const float x2 = p[d + 64];
        p[d]      = tf32_round(x1 * c - x2 * si);
        p[d + 64] = tf32_round(x2 * c + x1 * si);
    }
    // v (round only)
    {
        float* p = base + 2 * HD;
        p[d]      = tf32_round(p[d]);
        p[d + 64] = tf32_round(p[d + 64]);
    }
}

// ---------------------------------------------------------------------------
// tf32 mma.sync flash attention (causal)
// CTA: 128 q-rows x 1 head, 256 threads (8 warps x 16 q-rows).
// K-tiles of 64, cp.async double-buffered. Operands pre-rounded to tf32 in
// memory -> no cvt on Q/K/V paths. Per-warp causal early-skip.
// ---------------------------------------------------------------------------
#define AQ 128
#define AK 64
#define QST 132
#define VST 136
#define QWRD (128 * QST)
#define KWRD (64 * QST)
#define VWRD (64 * VST)
#define ATTN_SMEM_BYTES ((QWRD + 2 * (KWRD + VWRD)) * 4)  // 204800 B

__global__ __launch_bounds__(256, 1) void attn_tc_kernel(
    const float* __restrict__ mixed, float* __restrict__ ctx)
{
    extern __shared__ float sf[];
    float* Qs = sf;
    const uint32_t smem_base = smem_to_u32(sf);

    const int tid  = threadIdx.x;
    const int wid  = tid >> 5;       // 0..7
    const int lane = tid & 31;
    const int lr = lane >> 2;
    const int lc = lane & 3;
    const int qt = gridDim.x - 1 - blockIdx.x;   // biggest tiles first
    const int h  = blockIdx.y;
    const int r0 = qt * AQ;
    const int m0 = wid * 16;
    const size_t hoff = (size_t)h * HEAD_W;

    auto load_kv = [&](int kt) {
        const int b = kt & 1;
        const uint32_t kb = smem_base + (uint32_t)(QWRD + b * (KWRD + VWRD)) * 4;
        const uint32_t vb = kb + KWRD * 4;
        const float* kg = mixed + (size_t)(kt * AK) * MIXED_W + hoff + HD;
        const float* vg = kg + HD;
#pragma unroll
        for (int it = 0; it < 8; it++) {
            const int u = tid + (it << 8);
            const int row = u >> 5, c4 = (u & 31) << 2;
            CP_ASYNC16(kb + (uint32_t)(row * QST + c4) * 4, kg + (size_t)row * MIXED_W + c4);
            CP_ASYNC16(vb + (uint32_t)(row * VST + c4) * 4, vg + (size_t)row * MIXED_W + c4);
        }
        CP_ASYNC_COMMIT();
    };

    load_kv(0);

    // stage Q via cp.async (pre-scaled, pre-rounded in rotary)
    {
        const float* qg = mixed + (size_t)r0 * MIXED_W + hoff;
#pragma unroll
        for (int it = 0; it < 16; it++) {
            const int u = tid + (it << 8);
            const int row = u >> 5, c4 = (u & 31) << 2;
            CP_ASYNC16(smem_base + (uint32_t)(row * QST + c4) * 4,
                       qg + (size_t)row * MIXED_W + c4);
        }
        CP_ASYNC_COMMIT();
    }

    const int nkt = (r0 >> 6) + 2;

    float co[16][4];
#pragma unroll
    for (int nt = 0; nt < 16; nt++)
#pragma unroll
        for (int r = 0; r < 4; r++) co[nt][r] = 0.f;
    float mrow[2] = {-1e30f, -1e30f};
    float lrow[2] = {0.f, 0.f};

    const int src1 = (lane & ~3) | (lc >> 1);
    const int src2 = src1 + 2;
    const bool podd = (lc & 1);

    for (int kt = 0; kt < nkt; kt++) {
        if (kt + 1 < nkt) { load_kv(kt + 1); CP_ASYNC_WAIT(1); }
        else              { CP_ASYNC_WAIT(0); }
        __syncthreads();

        const float* Ks = sf + QWRD + (size_t)(kt & 1) * (KWRD + VWRD);
        const float* Vs = Ks + KWRD;
        const int c0 = kt * AK;

        // per-warp causal early-skip: warp strip rows [r0+m0, r0+m0+15]
        if (c0 <= r0 + m0 + 15) {
            // ---- S = Q K^T ----
            float s[8][4];
#pragma unroll
            for (int nt = 0; nt < 8; nt++)
#pragma unroll
                for (int r = 0; r < 4; r++) s[nt][r] = 0.f;

#pragma unroll
            for (int ks = 0; ks < 16; ks++) {
                const int kc = ks * 8 + lc;
                const int row = m0 + lr;
                uint32_t af[4];
                af[0] = __float_as_uint(Qs[row * QST + kc]);
                af[1] = __float_as_uint(Qs[(row + 8) * QST + kc]);
                af[2] = __float_as_uint(Qs[row * QST + kc + 4]);
                af[3] = __float_as_uint(Qs[(row + 8) * QST + kc + 4]);
#pragma unroll
                for (int nt = 0; nt < 8; nt++) {
                    const int ncol = nt * 8 + lr;
                    uint32_t bf[2];
                    bf[0] = __float_as_uint(Ks[ncol * QST + kc]);
                    bf[1] = __float_as_uint(Ks[ncol * QST + kc + 4]);
                    mma_tf32(s[nt], af, bf);
                }
            }

            // ---- causal mask (tiles touching the warp's diagonal) ----
            if (c0 + AK - 1 > r0 + m0) {
                const int rga = r0 + m0 + lr;
                const int rgb = rga + 8;
#pragma unroll
                for (int nt = 0; nt < 8; nt++) {
                    const int cg0 = c0 + nt * 8 + lc * 2;
                    const int cg1 = cg0 + 1;
                    if (cg0 > rga) s[nt][0] = -1e30f;
                    if (cg1 > rga) s[nt][1] = -1e30f;
                    if (cg0 > rgb) s[nt][2] = -1e30f;
                    if (cg1 > rgb) s[nt][3] = -1e30f;
                }
            }

            // ---- online softmax ----
#pragma unroll
            for (int hh = 0; hh < 2; hh++) {
                float mx = -1e30f;
#pragma unroll
                for (int nt = 0; nt < 8; nt++)
                    mx = fmaxf(mx, fmaxf(s[nt][2 * hh], s[nt][2 * hh + 1]));
                mx = fmaxf(mx, __shfl_xor_sync(0xffffffffu, mx, 1));
                mx = fmaxf(mx, __shfl_xor_sync(0xffffffffu, mx, 2));
                const float m_new = fmaxf(mrow[hh], mx);
                const float sc = __expf(mrow[hh] - m_new);
                float rs = 0.f;
#pragma unroll
                for (int nt = 0; nt < 8; nt++) {
                    const float p0 = __expf(s[nt][2 * hh] - m_new);
                    const float p1 = __expf(s[nt][2 * hh + 1] - m_new);
                    s[nt][2 * hh] = p0;
                    s[nt][2 * hh + 1] = p1;
                    rs += p0 + p1;
                }
                rs += __shfl_xor_sync(0xffffffffu, rs, 1);
                rs += __shfl_xor_sync(0xffffffffu, rs, 2);
                lrow[hh] = lrow[hh] * sc + rs;
                mrow[hh] = m_new;
#pragma unroll
                for (int nt = 0; nt < 16; nt++) {
                    co[nt][2 * hh]     *= sc;
                    co[nt][2 * hh + 1] *= sc;
                }
            }

            // ---- O += P V ----
#pragma unroll
            for (int kg = 0; kg < 8; kg++) {
                uint32_t pa[4];
                {
                    const float x0 = __shfl_sync(0xffffffffu, s[kg][0], src1);
                    const float x1 = __shfl_sync(0xffffffffu, s[kg][1], src1);
                    pa[0] = f32_to_tf32(podd ? x1 : x0);
                    const float x2 = __shfl_sync(0xffffffffu, s[kg][2], src1);
                    const float x3 = __shfl_sync(0xffffffffu, s[kg][3], src1);
                    pa[1] = f32_to_tf32(podd ? x3 : x2);
                    const float y0 = __shfl_sync(0xffffffffu, s[kg][0], src2);
                    const float y1 = __shfl_sync(0xffffffffu, s[kg][1], src2);
                    pa[2] = f32_to_tf32(podd ? y1 : y0);
                    const float y2 = __shfl_sync(0xffffffffu, s[kg][2], src2);
                    const float y3 = __shfl_sync(0xffffffffu, s[kg][3], src2);
                    pa[3] = f32_to_tf32(podd ? y3 : y2);
                }
#pragma unroll
                for (int nt = 0; nt < 16; nt++) {
                    uint32_t vb[2];
                    vb[0] = __float_as_uint(Vs[(kg * 8 + lc) * VST + nt * 8 + lr]);
                    vb[1] = __float_as_uint(Vs[(kg * 8 + lc + 4) * VST + nt * 8 + lr]);
                    mma_tf32(co[nt], pa, vb);
                }
            }
        }
        __syncthreads();
    }

    // ---- normalize + store ----
    {
        const float li0 = 1.f / lrow[0];
        const float li1 = 1.f / lrow[1];
        const int row = r0 + m0 + lr;
#pragma unroll
        for (int nt = 0; nt < 16; nt++) {
            const int col = h * HD + nt * 8 + lc * 2;
            *(float2*)(ctx + (size_t)row * H + col) =
                make_float2(co[nt][0] * li0, co[nt][1] * li0);
            *(float2*)(ctx + (size_t)(row + 8) * H + col) =
                make_float2(co[nt][2] * li1, co[nt][3] * li1);
        }
    }
}

// ---------------------------------------------------------------------------
// Launch
// ---------------------------------------------------------------------------
extern "C" void kernel_launch(void* const* d_in, const int* in_sizes, int n_in,
                              void* d_out, int out_size)
{
    const float* hidden  = (const float*)d_in[0];
    const float* w_qkv   = (const float*)d_in[2];
    const float* b_qkv   = (const float*)d_in[3];
    const float* w_dense = (const float*)d_in[4];
    float* out = (float*)d_out;

    float* mixed; float* ctx;
    cudaGetSymbolAddress((void**)&mixed, g_mixed);
    cudaGetSymbolAddress((void**)&ctx, g_ctx);

    cudaFuncSetAttribute(gemm_tc_kernel,
                         cudaFuncAttributeMaxDynamicSharedMemorySize, GT_SMEM_BYTES);
    cudaFuncSetAttribute(attn_tc_kernel,
                         cudaFuncAttributeMaxDynamicSharedMemorySize, ATTN_SMEM_BYTES);

    // 1) QKV projection (tf32 mma.sync)
    {
        dim3 grid(QKV_N / 128, S / 128);
        gemm_tc_kernel<<<grid, 256, GT_SMEM_BYTES>>>(hidden, w_qkv, b_qkv, mixed, S, QKV_N, H);
    }

    // 2) Rotary + tf32 pre-round
    {
        dim3 grid(S, NH);
        rotary_kernel<<<grid, 64>>>(mixed);
    }

    // 3) Causal flash attention (tf32 mma.sync)
    {
        dim3 grid(S / AQ, NH);
        attn_tc_kernel<<<grid, 256, ATTN_SMEM_BYTES>>>(mixed, ctx);
    }

    // 4) Dense projection (tf32 mma.sync)
    {
        dim3 grid(H / 128, S / 128);
        gemm_tc_kernel<<<grid, 256, GT_SMEM_BYTES>>>(ctx, w_dense, nullptr, out, S, H, H);
    }
}